// round 15
// baseline (speedup 1.0000x reference)
#include <cuda_runtime.h>
#include <cuda_fp16.h>
#include <math.h>
#include <stdint.h>

#define Bb   4
#define Dd   64
#define Hh   4
#define DHd  16
#define Nn   2304
#define BHh  16   // B*heads

#define LOG2E 1.4426950408889634f
#define SC    0.8493218593f   // sqrt(0.5*log2e)

// ---------------- scratch (device globals) ----------------------------------
__device__ uint32_t d_qb[BHh * Nn * 8];          // q f16x2: [bh][n][k/2], scaled by SC
__device__ float d_qn[BHh * Nn];                 // 0.25*log2e*||q||^2
__device__ __half d_zh[BHh * DHd * Nn];          // Z f16: [bh][c][m]
__device__ float d_u[BHh * Nn * DHd];            // U permuted: row' = (n%36)*64 + n/36
__device__ float d_cat[Bb * Dd * Nn];            // cat_img[b][dd][n]
__device__ float d_bound[1];

__device__ __forceinline__ uint32_t smem_u32(const void* p) {
    return (uint32_t)__cvta_generic_to_shared(p);
}
__device__ __forceinline__ void ldsm4(uint32_t& r0, uint32_t& r1, uint32_t& r2, uint32_t& r3,
                                      uint32_t addr) {
    asm volatile("ldmatrix.sync.aligned.m8n8.x4.shared.b16 {%0,%1,%2,%3}, [%4];"
                 : "=r"(r0), "=r"(r1), "=r"(r2), "=r"(r3) : "r"(addr));
}
__device__ __forceinline__ void mma16816h(float& d0, float& d1, float& d2, float& d3,
                                          uint32_t a0, uint32_t a1, uint32_t a2, uint32_t a3,
                                          uint32_t b0, uint32_t b1,
                                          float c0, float c1, float c2, float c3) {
    asm volatile("mma.sync.aligned.m16n8k16.row.col.f32.f16.f16.f32 "
                 "{%0,%1,%2,%3},{%4,%5,%6,%7},{%8,%9},{%10,%11,%12,%13};"
                 : "=f"(d0), "=f"(d1), "=f"(d2), "=f"(d3)
                 : "r"(a0), "r"(a1), "r"(a2), "r"(a3), "r"(b0), "r"(b1),
                   "f"(c0), "f"(c1), "f"(c2), "f"(c3));
}
__device__ __forceinline__ uint32_t h2u(__half2 h) {
    return *reinterpret_cast<uint32_t*>(&h);
}

// ---------------- K_qz: z==0 -> q all heads; z==1 -> Z all heads; z==2 -> bound
__global__ void __launch_bounds__(128) k_qz(const float* __restrict__ x,
                                            const float* __restrict__ Wq,
                                            const float* __restrict__ bq,
                                            const float* __restrict__ Wv,
                                            const float* __restrict__ Wo) {
    __shared__ float sW[Hh * DHd * Dd];   // 4096 floats: all heads
    int tid = threadIdx.x;
    int z = blockIdx.z;
    int b = blockIdx.y;

    if (z == 2) {
        if (blockIdx.x != 0 || blockIdx.y != 0) return;
        __shared__ float red[128];
        __shared__ float sq[Hh], sv[Hh];
        for (int h = 0; h < Hh; h++) {
            float a = 0.f;
            for (int i = tid; i < 1024; i += 128) { float w = Wq[h * 1024 + i]; a += w * w; }
            red[tid] = a; __syncthreads();
            for (int s = 64; s > 0; s >>= 1) { if (tid < s) red[tid] += red[tid + s]; __syncthreads(); }
            if (tid == 0) sq[h] = red[0];
            __syncthreads();
            a = 0.f;
            for (int i = tid; i < 1024; i += 128) { float w = Wv[h * 1024 + i]; a += w * w; }
            red[tid] = a; __syncthreads();
            for (int s = 64; s > 0; s >>= 1) { if (tid < s) red[tid] += red[tid + s]; __syncthreads(); }
            if (tid == 0) sv[h] = red[0];
            __syncthreads();
        }
        float a = 0.f;
        for (int i = tid; i < 4096; i += 128) { float w = Wo[i]; a += w * w; }
        red[tid] = a; __syncthreads();
        for (int s = 64; s > 0; s >>= 1) { if (tid < s) red[tid] += red[tid + s]; __syncthreads(); }
        if (tid == 0) {
            double zz = 2304.0 / 2.718281828459045;
            double w = log(zz) - log(log(zz));
            for (int it = 0; it < 30; it++) {
                double ew = exp(w);
                w = w - (w * ew - zz) / (ew * (w + 1.0));
            }
            float phi = (float)w;
            float term = sqrtf(sq[0] * sv[0] + sq[1] * sv[1] + sq[2] * sv[2] + sq[3] * sv[3]);
            d_bound[0] = sqrtf(2304.f / 64.f) * (4.f * phi + 1.f) * term * sqrtf(red[0]);
        }
        return;
    }

    for (int i = tid; i < 4096; i += 128) sW[i] = Wq[i];
    __syncthreads();

    if (z == 0) {
        int n = blockIdx.x * 128 + tid;
        const float* xb = x + b * Dd * Nn;
        float xv[Dd];
#pragma unroll
        for (int d = 0; d < Dd; d++) xv[d] = xb[d * Nn + n];
        for (int h = 0; h < Hh; h++) {
            int bh = b * Hh + h;
            float qv[DHd];
            float qn = 0.f;
#pragma unroll
            for (int k = 0; k < DHd; k++) {
                float acc = bq[h * DHd + k];
                const float* w = sW + (h * DHd + k) * Dd;
#pragma unroll
                for (int d = 0; d < Dd; d++) acc += w[d] * xv[d];
                qv[k] = acc;
                qn += acc * acc;
            }
            uint32_t pk[8];
#pragma unroll
            for (int i = 0; i < 8; i++)
                pk[i] = h2u(__floats2half2_rn(SC * qv[2 * i], SC * qv[2 * i + 1]));
            uint4* dst = (uint4*)(d_qb + ((size_t)bh * Nn + n) * 8);
            dst[0] = make_uint4(pk[0], pk[1], pk[2], pk[3]);
            dst[1] = make_uint4(pk[4], pk[5], pk[6], pk[7]);
            d_qn[(size_t)bh * Nn + n] = qn * (0.25f * LOG2E);
        }
    } else {
        int m = blockIdx.x * 128 + tid;
        const float* xr = x + (size_t)b * Dd * Nn + (size_t)m * Dd;
        float xv[Dd];
#pragma unroll
        for (int dc = 0; dc < 16; dc++) {
            float4 v = *(const float4*)(xr + dc * 4);
            xv[dc * 4 + 0] = v.x; xv[dc * 4 + 1] = v.y;
            xv[dc * 4 + 2] = v.z; xv[dc * 4 + 3] = v.w;
        }
        for (int h = 0; h < Hh; h++) {
            int bh = b * Hh + h;
            float acc[DHd];
#pragma unroll
            for (int c = 0; c < DHd; c++) acc[c] = 0.f;
#pragma unroll
            for (int d = 0; d < Dd; d++) {
                float xd = xv[d];
                const float4* rr = (const float4*)(sW + h * 1024 + d * 16);
#pragma unroll
                for (int cc = 0; cc < 4; cc++) {
                    float4 rv = rr[cc];
                    acc[cc * 4 + 0] += xd * rv.x;
                    acc[cc * 4 + 1] += xd * rv.y;
                    acc[cc * 4 + 2] += xd * rv.z;
                    acc[cc * 4 + 3] += xd * rv.w;
                }
            }
#pragma unroll
            for (int c = 0; c < DHd; c++)
                d_zh[((size_t)bh * DHd + c) * Nn + m] = __float2half_rn(acc[c]);
        }
    }
}

// ---------------- K1: flash, f16 MMAs + packed-half exp ----------------------
__global__ void __launch_bounds__(256) k_flash() {
    int bh = blockIdx.y;
    int n0 = blockIdx.x * 128;
    int tid = threadIdx.x;
    int w = tid >> 5, lane = tid & 31;
    int grp = lane >> 3, lr = lane & 7;

    __shared__ __align__(16) __half sQ[128 * 24];     // rows n, pitch 24
    __shared__ __align__(16) __half sK[2][64 * 24];   // rows m, pitch 24
    __shared__ __align__(16) __half sZ[2][16 * 72];   // rows c, pitch 72
    __shared__ float sKn[2][64];

    const uint4* qb4 = (const uint4*)d_qb + (size_t)bh * Nn * 2;
    const __half* zb = d_zh + (size_t)bh * DHd * Nn;
    const float* qnb = d_qn + (size_t)bh * Nn;

    int krow = tid >> 1, khalf = tid & 1;
    int zc = (tid - 128) >> 3, zseg = (tid - 128) & 7;

    {
        int row = tid >> 1, half = tid & 1;
        *(uint4*)(sQ + row * 24 + half * 8) = qb4[(size_t)(n0 + row) * 2 + half];
    }
    if (tid < 128) *(uint4*)(sK[0] + krow * 24 + khalf * 8) = qb4[krow * 2 + khalf];
    else           *(uint4*)(sZ[0] + zc * 72 + zseg * 8) = *(const uint4*)(zb + (size_t)zc * Nn + zseg * 8);
    if (tid < 64)  sKn[0][tid] = qnb[tid];
    __syncthreads();

    uint32_t qa0, qa1, qa2, qa3;
    {
        uint32_t addr = smem_u32(sQ) + ((w * 16 + (grp & 1) * 8 + lr) * 24 + (grp >> 1) * 8) * 2;
        ldsm4(qa0, qa1, qa2, qa3, addr);
    }
    float nq0 = -qnb[n0 + w * 16 + (lane >> 2)];
    float nq1 = -qnb[n0 + w * 16 + (lane >> 2) + 8];

    uint32_t AKb0 = smem_u32(sK[0]) + (((grp >> 1) * 8 + lr) * 24 + (grp & 1) * 8) * 2;
    uint32_t AZb0 = smem_u32(sZ[0]) + ((grp >> 1) * 8 + lr) * 144 + ((grp & 1) * 8) * 2;
    const uint32_t KBUF = 64 * 24 * 2, ZBUF = 16 * 72 * 2;

    float O[2][4];
#pragma unroll
    for (int u = 0; u < 2; u++)
#pragma unroll
        for (int k = 0; k < 4; k++) O[u][k] = 0.f;
    __half2 li2_0 = __floats2half2_rn(0.f, 0.f);
    __half2 li2_1 = __floats2half2_rn(0.f, 0.f);

    for (int t = 0; t < 36; t++) {
        int cur = t & 1;
        uint4 pK, pZ;
        float pN;
        if (t < 35) {
            int m0 = (t + 1) * 64;
            if (tid < 128) pK = qb4[(size_t)(m0 + krow) * 2 + khalf];
            else           pZ = *(const uint4*)(zb + (size_t)zc * Nn + m0 + zseg * 8);
            if (tid < 64)  pN = qnb[m0 + tid];
        }

        uint32_t kf[8][2];
#pragma unroll
        for (int s = 0; s < 4; s++) {
            uint32_t r0, r1, r2, r3;
            ldsm4(r0, r1, r2, r3, AKb0 + cur * KBUF + s * 768);
            kf[2 * s][0] = r0; kf[2 * s][1] = r1;
            kf[2 * s + 1][0] = r2; kf[2 * s + 1][1] = r3;
        }

        // S mmas + packed-half softmax: pe[j][0]=exp2 of (row r, cols 2), pe[j][1]=row r+8
        uint32_t pe[8][2];
#pragma unroll
        for (int j = 0; j < 8; j++) {
            float2 kn2 = *(const float2*)&sKn[cur][8 * j + 2 * (lane & 3)];
            float d0, d1, d2, d3;
            mma16816h(d0, d1, d2, d3, qa0, qa1, qa2, qa3, kf[j][0], kf[j][1],
                      nq0 - kn2.x, nq0 - kn2.y, nq1 - kn2.x, nq1 - kn2.y);
            __half2 e01 = h2exp2(__floats2half2_rn(d0, d1));
            __half2 e23 = h2exp2(__floats2half2_rn(d2, d3));
            li2_0 = __hadd2(li2_0, e01);
            li2_1 = __hadd2(li2_1, e23);
            pe[j][0] = h2u(e01);
            pe[j][1] = h2u(e23);
        }

        // PV mmas (P already in f16 fragments)
#pragma unroll
        for (int s = 0; s < 4; s++) {
            uint32_t z0, z1, z2, z3;
            ldsm4(z0, z1, z2, z3, AZb0 + cur * ZBUF + s * 32);
            mma16816h(O[0][0], O[0][1], O[0][2], O[0][3],
                      pe[2 * s][0], pe[2 * s][1], pe[2 * s + 1][0], pe[2 * s + 1][1],
                      z0, z1, O[0][0], O[0][1], O[0][2], O[0][3]);
            mma16816h(O[1][0], O[1][1], O[1][2], O[1][3],
                      pe[2 * s][0], pe[2 * s][1], pe[2 * s + 1][0], pe[2 * s + 1][1],
                      z2, z3, O[1][0], O[1][1], O[1][2], O[1][3]);
        }

        if (t < 35) {
            int nxt = 1 - cur;
            if (tid < 128) *(uint4*)(sK[nxt] + krow * 24 + khalf * 8) = pK;
            else           *(uint4*)(sZ[nxt] + zc * 72 + zseg * 8) = pZ;
            if (tid < 64)  sKn[nxt][tid] = pN;
        }
        __syncthreads();
    }

    float li0 = __low2float(li2_0) + __high2float(li2_0);
    float li1 = __low2float(li2_1) + __high2float(li2_1);
    li0 += __shfl_xor_sync(0xffffffffu, li0, 1);
    li0 += __shfl_xor_sync(0xffffffffu, li0, 2);
    li1 += __shfl_xor_sync(0xffffffffu, li1, 1);
    li1 += __shfl_xor_sync(0xffffffffu, li1, 2);

    float i0 = 1.f / li0, i1 = 1.f / li1;
    int r0 = n0 + w * 16 + (lane >> 2);
    int r1 = r0 + 8;
    int pr0 = (r0 % 36) * 64 + r0 / 36;
    int pr1 = (r1 % 36) * 64 + r1 / 36;
    int cb = 2 * (lane & 3);
    float* ur0 = d_u + ((size_t)bh * Nn + pr0) * 16;
    float* ur1 = d_u + ((size_t)bh * Nn + pr1) * 16;
    *(float2*)(ur0 + cb)     = make_float2(O[0][0] * i0, O[0][1] * i0);
    *(float2*)(ur0 + cb + 8) = make_float2(O[1][0] * i0, O[1][1] * i0);
    *(float2*)(ur1 + cb)     = make_float2(O[0][2] * i1, O[0][3] * i1);
    *(float2*)(ur1 + cb + 8) = make_float2(O[1][2] * i1, O[1][3] * i1);
}

// ---------------- K_gv: fused g/v, writes directly into cat layout ----------
__global__ void __launch_bounds__(256) k_gv(const float* __restrict__ Wq,
                                            const float* __restrict__ Wv,
                                            const float* __restrict__ bv) {
    int bh = blockIdx.y;
    int h = bh & 3;
    int b = bh >> 2;
    int a = blockIdx.x;
    int tid = threadIdx.x;

    __shared__ float sT[64][17];
    __shared__ float sWv[1024];
    __shared__ float sR[64][17];
    __shared__ float sM[16][17];

    int r_ = tid & 63, kg_ = tid >> 6;
    float bvv[4];
#pragma unroll
    for (int kk2 = 0; kk2 < 4; kk2++) bvv[kk2] = bv[h * 16 + kg_ * 4 + kk2];

    {
        int dd = tid >> 2, cg = tid & 3;
        float4 v = *(const float4*)(d_u + ((size_t)bh * Nn + a * 64 + dd) * 16 + cg * 4);
        sT[dd][cg * 4 + 0] = v.x; sT[dd][cg * 4 + 1] = v.y;
        sT[dd][cg * 4 + 2] = v.z; sT[dd][cg * 4 + 3] = v.w;
        float4 rv = *(const float4*)(Wq + h * 1024 + dd * 16 + cg * 4);
        sR[dd][cg * 4 + 0] = rv.x; sR[dd][cg * 4 + 1] = rv.y;
        sR[dd][cg * 4 + 2] = rv.z; sR[dd][cg * 4 + 3] = rv.w;
    }
    for (int i = tid; i < 1024; i += 256) sWv[i] = Wv[h * 1024 + i];
    __syncthreads();

    {
        int k = tid >> 4, c = tid & 15;
        float acc = 0.f;
#pragma unroll
        for (int dd = 0; dd < 64; dd++) acc += sWv[k * 64 + dd] * sT[dd][c];
        sM[k][c] = acc;
    }
    __syncthreads();

    {
        float vacc[4] = {0.f, 0.f, 0.f, 0.f};
#pragma unroll
        for (int c = 0; c < 16; c++) {
            float rc = sR[r_][c];
            vacc[0] += sM[kg_ * 4 + 0][c] * rc;
            vacc[1] += sM[kg_ * 4 + 1][c] * rc;
            vacc[2] += sM[kg_ * 4 + 2][c] * rc;
            vacc[3] += sM[kg_ * 4 + 3][c] * rc;
        }
        int rq = r_ >> 4, kkl = r_ & 15;
#pragma unroll
        for (int kk2 = 0; kk2 < 4; kk2++) {
            int k = kg_ * 4 + kk2;
            float val = bvv[kk2] + 0.25f * vacc[kk2];
            int s = k * 144 + a * 4 + rq;
            int dd_c = s / 36;
            int a_c = s - dd_c * 36;
            int n_c = a_c * 64 + h * 16 + kkl;
            d_cat[((size_t)(b * 64 + dd_c)) * Nn + n_c] = val;
        }
    }
}

// ---------------- K_out: 64(n) x 16(o) tiles, 576 blocks, early x prefetch --
__global__ void __launch_bounds__(256) k_out(const float* __restrict__ Wo,
                                             const float* __restrict__ bo,
                                             const float* __restrict__ gamma,
                                             const float* __restrict__ x,
                                             float* __restrict__ out) {
    int b = blockIdx.y;
    int n0 = blockIdx.x * 64;
    int ob = blockIdx.z * 16;
    int tid = threadIdx.x, ty = tid >> 4, tx = tid & 15;
    __shared__ __align__(16) float sC[64][68];
    __shared__ __align__(16) float sW[16][64];

    int o = ob + ty;
    size_t base = ((size_t)b * 64 + o) * Nn + n0 + tx * 4;
    float4 xin = *(const float4*)(&x[base]);
    float g0 = gamma[0];
    float bnd = d_bound[0];
    float bb = bo[o];

    for (int i = tid; i < 1024; i += 256) {
        int dd = i >> 4, jj = (i & 15) * 4;
        *(float4*)(&sC[dd][jj]) = *(const float4*)(d_cat + ((size_t)(b * 64 + dd)) * Nn + n0 + jj);
    }
    {
        int row = tid >> 4, col = (tid & 15) * 4;
        *(float4*)(&sW[row][col]) = *(const float4*)(Wo + (ob + row) * 64 + col);
    }
    __syncthreads();
    float a0 = 0.f, a1 = 0.f, a2 = 0.f, a3 = 0.f;
#pragma unroll 16
    for (int dd = 0; dd < 64; dd++) {
        float wv = sW[ty][dd];
        float4 cv = *(const float4*)(&sC[dd][tx * 4]);
        a0 += wv * cv.x;
        a1 += wv * cv.y;
        a2 += wv * cv.z;
        a3 += wv * cv.w;
    }
    float scale = g0 / bnd;
    float4 r;
    r.x = scale * (a0 + bb) + xin.x;
    r.y = scale * (a1 + bb) + xin.y;
    r.z = scale * (a2 + bb) + xin.z;
    r.w = scale * (a3 + bb) + xin.w;
    *(float4*)(&out[base]) = r;
}

// ---------------- launch -----------------------------------------------------
extern "C" void kernel_launch(void* const* d_in, const int* in_sizes, int n_in,
                              void* d_out, int out_size) {
    const float* x     = (const float*)d_in[0];
    const float* Wq    = (const float*)d_in[1];
    const float* bq    = (const float*)d_in[2];
    const float* Wv    = (const float*)d_in[3];
    const float* bv    = (const float*)d_in[4];
    const float* Wo    = (const float*)d_in[5];
    const float* bo    = (const float*)d_in[6];
    const float* gamma = (const float*)d_in[7];
    float* out = (float*)d_out;

    k_qz   <<<dim3(Nn / 128, Bb, 3), 128>>>(x, Wq, bq, Wv, Wo);
    k_flash<<<dim3(Nn / 128, BHh), 256>>>();
    k_gv   <<<dim3(36, BHh), 256>>>(Wq, Wv, bv);
    k_out  <<<dim3(Nn / 64, Bb, 4), 256>>>(Wo, bo, gamma, x, out);
}

// round 16
// speedup vs baseline: 1.1025x; 1.1025x over previous
#include <cuda_runtime.h>
#include <cuda_fp16.h>
#include <math.h>
#include <stdint.h>

#define Bb   4
#define Dd   64
#define Hh   4
#define DHd  16
#define Nn   2304
#define BHh  16   // B*heads

#define LOG2E 1.4426950408889634f
#define SC    0.8493218593f   // sqrt(0.5*log2e)

// ---------------- scratch (device globals) ----------------------------------
__device__ uint32_t d_qb[BHh * Nn * 8];          // q f16x2: [bh][n][k/2], scaled by SC
__device__ float d_qn[BHh * Nn];                 // 0.25*log2e*||q||^2
__device__ __half d_zh[BHh * DHd * Nn];          // Z f16: [bh][c][m]
__device__ float d_u[BHh * Nn * DHd];            // U permuted: row' = (n%36)*64 + n/36
__device__ float d_cat[Bb * Dd * Nn];            // cat_img[b][dd][n]
__device__ float d_bound[1];

__device__ __forceinline__ uint32_t smem_u32(const void* p) {
    return (uint32_t)__cvta_generic_to_shared(p);
}
__device__ __forceinline__ void ldsm4(uint32_t& r0, uint32_t& r1, uint32_t& r2, uint32_t& r3,
                                      uint32_t addr) {
    asm volatile("ldmatrix.sync.aligned.m8n8.x4.shared.b16 {%0,%1,%2,%3}, [%4];"
                 : "=r"(r0), "=r"(r1), "=r"(r2), "=r"(r3) : "r"(addr));
}
// f16-accumulate HMMA: D,C are 2 regs (f16x2 pairs: {row r: c0,c1}, {row r+8: c0,c1})
__device__ __forceinline__ void mma16816hh(uint32_t& d0, uint32_t& d1,
                                           uint32_t a0, uint32_t a1, uint32_t a2, uint32_t a3,
                                           uint32_t b0, uint32_t b1,
                                           uint32_t c0, uint32_t c1) {
    asm volatile("mma.sync.aligned.m16n8k16.row.col.f16.f16.f16.f16 "
                 "{%0,%1},{%2,%3,%4,%5},{%6,%7},{%8,%9};"
                 : "=r"(d0), "=r"(d1)
                 : "r"(a0), "r"(a1), "r"(a2), "r"(a3), "r"(b0), "r"(b1),
                   "r"(c0), "r"(c1));
}
__device__ __forceinline__ uint32_t h2u(__half2 h) {
    return *reinterpret_cast<uint32_t*>(&h);
}
__device__ __forceinline__ __half2 u2h(uint32_t u) {
    return *reinterpret_cast<__half2*>(&u);
}

// ---------------- K_qz: z==0 -> q all heads; z==1 -> Z all heads; z==2 -> bound
__global__ void __launch_bounds__(128) k_qz(const float* __restrict__ x,
                                            const float* __restrict__ Wq,
                                            const float* __restrict__ bq,
                                            const float* __restrict__ Wv,
                                            const float* __restrict__ Wo) {
    __shared__ float sW[Hh * DHd * Dd];   // 4096 floats: all heads
    int tid = threadIdx.x;
    int z = blockIdx.z;
    int b = blockIdx.y;

    if (z == 2) {
        if (blockIdx.x != 0 || blockIdx.y != 0) return;
        __shared__ float red[128];
        __shared__ float sq[Hh], sv[Hh];
        for (int h = 0; h < Hh; h++) {
            float a = 0.f;
            for (int i = tid; i < 1024; i += 128) { float w = Wq[h * 1024 + i]; a += w * w; }
            red[tid] = a; __syncthreads();
            for (int s = 64; s > 0; s >>= 1) { if (tid < s) red[tid] += red[tid + s]; __syncthreads(); }
            if (tid == 0) sq[h] = red[0];
            __syncthreads();
            a = 0.f;
            for (int i = tid; i < 1024; i += 128) { float w = Wv[h * 1024 + i]; a += w * w; }
            red[tid] = a; __syncthreads();
            for (int s = 64; s > 0; s >>= 1) { if (tid < s) red[tid] += red[tid + s]; __syncthreads(); }
            if (tid == 0) sv[h] = red[0];
            __syncthreads();
        }
        float a = 0.f;
        for (int i = tid; i < 4096; i += 128) { float w = Wo[i]; a += w * w; }
        red[tid] = a; __syncthreads();
        for (int s = 64; s > 0; s >>= 1) { if (tid < s) red[tid] += red[tid + s]; __syncthreads(); }
        if (tid == 0) {
            double zz = 2304.0 / 2.718281828459045;
            double w = log(zz) - log(log(zz));
            for (int it = 0; it < 30; it++) {
                double ew = exp(w);
                w = w - (w * ew - zz) / (ew * (w + 1.0));
            }
            float phi = (float)w;
            float term = sqrtf(sq[0] * sv[0] + sq[1] * sv[1] + sq[2] * sv[2] + sq[3] * sv[3]);
            d_bound[0] = sqrtf(2304.f / 64.f) * (4.f * phi + 1.f) * term * sqrtf(red[0]);
        }
        return;
    }

    for (int i = tid; i < 4096; i += 128) sW[i] = Wq[i];
    __syncthreads();

    if (z == 0) {
        int n = blockIdx.x * 128 + tid;
        const float* xb = x + b * Dd * Nn;
        float xv[Dd];
#pragma unroll
        for (int d = 0; d < Dd; d++) xv[d] = xb[d * Nn + n];
        for (int h = 0; h < Hh; h++) {
            int bh = b * Hh + h;
            float qv[DHd];
            float qn = 0.f;
#pragma unroll
            for (int k = 0; k < DHd; k++) {
                float acc = bq[h * DHd + k];
                const float* w = sW + (h * DHd + k) * Dd;
#pragma unroll
                for (int d = 0; d < Dd; d++) acc += w[d] * xv[d];
                qv[k] = acc;
                qn += acc * acc;
            }
            uint32_t pk[8];
#pragma unroll
            for (int i = 0; i < 8; i++)
                pk[i] = h2u(__floats2half2_rn(SC * qv[2 * i], SC * qv[2 * i + 1]));
            uint4* dst = (uint4*)(d_qb + ((size_t)bh * Nn + n) * 8);
            dst[0] = make_uint4(pk[0], pk[1], pk[2], pk[3]);
            dst[1] = make_uint4(pk[4], pk[5], pk[6], pk[7]);
            d_qn[(size_t)bh * Nn + n] = qn * (0.25f * LOG2E);
        }
    } else {
        int m = blockIdx.x * 128 + tid;
        const float* xr = x + (size_t)b * Dd * Nn + (size_t)m * Dd;
        float xv[Dd];
#pragma unroll
        for (int dc = 0; dc < 16; dc++) {
            float4 v = *(const float4*)(xr + dc * 4);
            xv[dc * 4 + 0] = v.x; xv[dc * 4 + 1] = v.y;
            xv[dc * 4 + 2] = v.z; xv[dc * 4 + 3] = v.w;
        }
        for (int h = 0; h < Hh; h++) {
            int bh = b * Hh + h;
            float acc[DHd];
#pragma unroll
            for (int c = 0; c < DHd; c++) acc[c] = 0.f;
#pragma unroll
            for (int d = 0; d < Dd; d++) {
                float xd = xv[d];
                const float4* rr = (const float4*)(sW + h * 1024 + d * 16);
#pragma unroll
                for (int cc = 0; cc < 4; cc++) {
                    float4 rv = rr[cc];
                    acc[cc * 4 + 0] += xd * rv.x;
                    acc[cc * 4 + 1] += xd * rv.y;
                    acc[cc * 4 + 2] += xd * rv.z;
                    acc[cc * 4 + 3] += xd * rv.w;
                }
            }
#pragma unroll
            for (int c = 0; c < DHd; c++)
                d_zh[((size_t)bh * DHd + c) * Nn + m] = __float2half_rn(acc[c]);
        }
    }
}

// ---------------- K1: flash, all-f16 HMMA + direct h2exp2 --------------------
__global__ void __launch_bounds__(256) k_flash() {
    int bh = blockIdx.y;
    int n0 = blockIdx.x * 128;
    int tid = threadIdx.x;
    int w = tid >> 5, lane = tid & 31;
    int grp = lane >> 3, lr = lane & 7;

    __shared__ __align__(16) __half sQ[128 * 24];     // rows n, pitch 24
    __shared__ __align__(16) __half sK[2][64 * 24];   // rows m, pitch 24
    __shared__ __align__(16) __half sZ[2][16 * 72];   // rows c, pitch 72
    __shared__ uint32_t sKn2[2][32];                  // packed (-qnl_m) half2 pairs

    const uint4* qb4 = (const uint4*)d_qb + (size_t)bh * Nn * 2;
    const __half* zb = d_zh + (size_t)bh * DHd * Nn;
    const float* qnb = d_qn + (size_t)bh * Nn;

    int krow = tid >> 1, khalf = tid & 1;
    int zc = (tid - 128) >> 3, zseg = (tid - 128) & 7;

    {
        int row = tid >> 1, half = tid & 1;
        *(uint4*)(sQ + row * 24 + half * 8) = qb4[(size_t)(n0 + row) * 2 + half];
    }
    if (tid < 128) *(uint4*)(sK[0] + krow * 24 + khalf * 8) = qb4[krow * 2 + khalf];
    else           *(uint4*)(sZ[0] + zc * 72 + zseg * 8) = *(const uint4*)(zb + (size_t)zc * Nn + zseg * 8);
    if (tid < 32) {
        float2 v = *(const float2*)(qnb + 2 * tid);
        sKn2[0][tid] = h2u(__floats2half2_rn(-v.x, -v.y));
    }
    __syncthreads();

    uint32_t qa0, qa1, qa2, qa3;
    {
        uint32_t addr = smem_u32(sQ) + ((w * 16 + (grp & 1) * 8 + lr) * 24 + (grp >> 1) * 8) * 2;
        ldsm4(qa0, qa1, qa2, qa3, addr);
    }
    __half2 nq0h = __float2half2_rn(-qnb[n0 + w * 16 + (lane >> 2)]);
    __half2 nq1h = __float2half2_rn(-qnb[n0 + w * 16 + (lane >> 2) + 8]);

    uint32_t AKb0 = smem_u32(sK[0]) + (((grp >> 1) * 8 + lr) * 24 + (grp & 1) * 8) * 2;
    uint32_t AZb0 = smem_u32(sZ[0]) + ((grp >> 1) * 8 + lr) * 144 + ((grp & 1) * 8) * 2;
    const uint32_t KBUF = 64 * 24 * 2, ZBUF = 16 * 72 * 2;

    uint32_t O2[2][2];   // [n-chunk][row-half], f16x2 accumulators
    const uint32_t ZERO2 = 0u;
#pragma unroll
    for (int u = 0; u < 2; u++) { O2[u][0] = ZERO2; O2[u][1] = ZERO2; }
    float li0 = 0.f, li1 = 0.f;

    for (int t = 0; t < 36; t++) {
        int cur = t & 1;
        uint4 pK, pZ;
        float2 pN;
        if (t < 35) {
            int m0 = (t + 1) * 64;
            if (tid < 128) pK = qb4[(size_t)(m0 + krow) * 2 + khalf];
            else           pZ = *(const uint4*)(zb + (size_t)zc * Nn + m0 + zseg * 8);
            if (tid < 32)  pN = *(const float2*)(qnb + m0 + 2 * tid);
        }

        uint32_t kf[8][2];
#pragma unroll
        for (int s = 0; s < 4; s++) {
            uint32_t r0, r1, r2, r3;
            ldsm4(r0, r1, r2, r3, AKb0 + cur * KBUF + s * 768);
            kf[2 * s][0] = r0; kf[2 * s][1] = r1;
            kf[2 * s + 1][0] = r2; kf[2 * s + 1][1] = r3;
        }

        // S mmas (f16 accum, bias in C) + direct packed exp
        uint32_t pe[8][2];
        __half2 tl0 = u2h(ZERO2), tl1 = u2h(ZERO2);
#pragma unroll
        for (int j = 0; j < 8; j++) {
            __half2 knh = u2h(sKn2[cur][4 * j + (lane & 3)]);
            uint32_t c0 = h2u(__hadd2(nq0h, knh));
            uint32_t c1 = h2u(__hadd2(nq1h, knh));
            uint32_t s0, s1;
            mma16816hh(s0, s1, qa0, qa1, qa2, qa3, kf[j][0], kf[j][1], c0, c1);
            __half2 e01 = h2exp2(u2h(s0));
            __half2 e23 = h2exp2(u2h(s1));
            tl0 = __hadd2(tl0, e01);
            tl1 = __hadd2(tl1, e23);
            pe[j][0] = h2u(e01);
            pe[j][1] = h2u(e23);
        }
        li0 += __low2float(tl0) + __high2float(tl0);
        li1 += __low2float(tl1) + __high2float(tl1);

        // PV mmas (f16 accum; P fragments = exp outputs directly)
#pragma unroll
        for (int s = 0; s < 4; s++) {
            uint32_t z0, z1, z2, z3;
            ldsm4(z0, z1, z2, z3, AZb0 + cur * ZBUF + s * 32);
            mma16816hh(O2[0][0], O2[0][1],
                       pe[2 * s][0], pe[2 * s][1], pe[2 * s + 1][0], pe[2 * s + 1][1],
                       z0, z1, O2[0][0], O2[0][1]);
            mma16816hh(O2[1][0], O2[1][1],
                       pe[2 * s][0], pe[2 * s][1], pe[2 * s + 1][0], pe[2 * s + 1][1],
                       z2, z3, O2[1][0], O2[1][1]);
        }

        if (t < 35) {
            int nxt = 1 - cur;
            if (tid < 128) *(uint4*)(sK[nxt] + krow * 24 + khalf * 8) = pK;
            else           *(uint4*)(sZ[nxt] + zc * 72 + zseg * 8) = pZ;
            if (tid < 32)  sKn2[nxt][tid] = h2u(__floats2half2_rn(-pN.x, -pN.y));
        }
        __syncthreads();
    }

    // unpack O to fp32: O[u][0..3] = (r,c0),(r,c1),(r+8,c0),(r+8,c1)
    float O[2][4];
#pragma unroll
    for (int u = 0; u < 2; u++) {
        float2 lo = __half22float2(u2h(O2[u][0]));
        float2 hi = __half22float2(u2h(O2[u][1]));
        O[u][0] = lo.x; O[u][1] = lo.y; O[u][2] = hi.x; O[u][3] = hi.y;
    }

    // quad-reduce (lanes in quad hold disjoint columns)
#pragma unroll
    for (int off = 2; off >= 1; off >>= 1) {
        li0 += __shfl_xor_sync(0xffffffffu, li0, off);
        li1 += __shfl_xor_sync(0xffffffffu, li1, off);
#pragma unroll
        for (int u = 0; u < 2; u++)
#pragma unroll
            for (int k = 0; k < 4; k++)
                O[u][k] += __shfl_xor_sync(0xffffffffu, O[u][k], off);
    }

    float i0 = 1.f / li0, i1 = 1.f / li1;
    int r0 = n0 + w * 16 + (lane >> 2);
    int r1 = r0 + 8;
    int pr0 = (r0 % 36) * 64 + r0 / 36;
    int pr1 = (r1 % 36) * 64 + r1 / 36;
    int cb = 2 * (lane & 3);
    float* ur0 = d_u + ((size_t)bh * Nn + pr0) * 16;
    float* ur1 = d_u + ((size_t)bh * Nn + pr1) * 16;
    *(float2*)(ur0 + cb)     = make_float2(O[0][0] * i0, O[0][1] * i0);
    *(float2*)(ur0 + cb + 8) = make_float2(O[1][0] * i0, O[1][1] * i0);
    *(float2*)(ur1 + cb)     = make_float2(O[0][2] * i1, O[0][3] * i1);
    *(float2*)(ur1 + cb + 8) = make_float2(O[1][2] * i1, O[1][3] * i1);
}

// ---------------- K_gv: fused g/v, writes directly into cat layout ----------
__global__ void __launch_bounds__(256) k_gv(const float* __restrict__ Wq,
                                            const float* __restrict__ Wv,
                                            const float* __restrict__ bv) {
    int bh = blockIdx.y;
    int h = bh & 3;
    int b = bh >> 2;
    int a = blockIdx.x;
    int tid = threadIdx.x;

    __shared__ float sT[64][17];
    __shared__ float sWv[1024];
    __shared__ float sR[64][17];
    __shared__ float sM[16][17];

    int r_ = tid & 63, kg_ = tid >> 6;
    float bvv[4];
#pragma unroll
    for (int kk2 = 0; kk2 < 4; kk2++) bvv[kk2] = bv[h * 16 + kg_ * 4 + kk2];

    {
        int dd = tid >> 2, cg = tid & 3;
        float4 v = *(const float4*)(d_u + ((size_t)bh * Nn + a * 64 + dd) * 16 + cg * 4);
        sT[dd][cg * 4 + 0] = v.x; sT[dd][cg * 4 + 1] = v.y;
        sT[dd][cg * 4 + 2] = v.z; sT[dd][cg * 4 + 3] = v.w;
        float4 rv = *(const float4*)(Wq + h * 1024 + dd * 16 + cg * 4);
        sR[dd][cg * 4 + 0] = rv.x; sR[dd][cg * 4 + 1] = rv.y;
        sR[dd][cg * 4 + 2] = rv.z; sR[dd][cg * 4 + 3] = rv.w;
    }
    for (int i = tid; i < 1024; i += 256) sWv[i] = Wv[h * 1024 + i];
    __syncthreads();

    {
        int k = tid >> 4, c = tid & 15;
        float acc = 0.f;
#pragma unroll
        for (int dd = 0; dd < 64; dd++) acc += sWv[k * 64 + dd] * sT[dd][c];
        sM[k][c] = acc;
    }
    __syncthreads();

    {
        float vacc[4] = {0.f, 0.f, 0.f, 0.f};
#pragma unroll
        for (int c = 0; c < 16; c++) {
            float rc = sR[r_][c];
            vacc[0] += sM[kg_ * 4 + 0][c] * rc;
            vacc[1] += sM[kg_ * 4 + 1][c] * rc;
            vacc[2] += sM[kg_ * 4 + 2][c] * rc;
            vacc[3] += sM[kg_ * 4 + 3][c] * rc;
        }
        int rq = r_ >> 4, kkl = r_ & 15;
#pragma unroll
        for (int kk2 = 0; kk2 < 4; kk2++) {
            int k = kg_ * 4 + kk2;
            float val = bvv[kk2] + 0.25f * vacc[kk2];
            int s = k * 144 + a * 4 + rq;
            int dd_c = s / 36;
            int a_c = s - dd_c * 36;
            int n_c = a_c * 64 + h * 16 + kkl;
            d_cat[((size_t)(b * 64 + dd_c)) * Nn + n_c] = val;
        }
    }
}

// ---------------- K_out: 64(n) x 16(o) tiles, 576 blocks, early x prefetch --
__global__ void __launch_bounds__(256) k_out(const float* __restrict__ Wo,
                                             const float* __restrict__ bo,
                                             const float* __restrict__ gamma,
                                             const float* __restrict__ x,
                                             float* __restrict__ out) {
    int b = blockIdx.y;
    int n0 = blockIdx.x * 64;
    int ob = blockIdx.z * 16;
    int tid = threadIdx.x, ty = tid >> 4, tx = tid & 15;
    __shared__ __align__(16) float sC[64][68];
    __shared__ __align__(16) float sW[16][64];

    int o = ob + ty;
    size_t base = ((size_t)b * 64 + o) * Nn + n0 + tx * 4;
    float4 xin = *(const float4*)(&x[base]);
    float g0 = gamma[0];
    float bnd = d_bound[0];
    float bb = bo[o];

    for (int i = tid; i < 1024; i += 256) {
        int dd = i >> 4, jj = (i & 15) * 4;
        *(float4*)(&sC[dd][jj]) = *(const float4*)(d_cat + ((size_t)(b * 64 + dd)) * Nn + n0 + jj);
    }
    {
        int row = tid >> 4, col = (tid & 15) * 4;
        *(float4*)(&sW[row][col]) = *(const float4*)(Wo + (ob + row) * 64 + col);
    }
    __syncthreads();
    float a0 = 0.f, a1 = 0.f, a2 = 0.f, a3 = 0.f;
#pragma unroll 16
    for (int dd = 0; dd < 64; dd++) {
        float wv = sW[ty][dd];
        float4 cv = *(const float4*)(&sC[dd][tx * 4]);
        a0 += wv * cv.x;
        a1 += wv * cv.y;
        a2 += wv * cv.z;
        a3 += wv * cv.w;
    }
    float scale = g0 / bnd;
    float4 r;
    r.x = scale * (a0 + bb) + xin.x;
    r.y = scale * (a1 + bb) + xin.y;
    r.z = scale * (a2 + bb) + xin.z;
    r.w = scale * (a3 + bb) + xin.w;
    *(float4*)(&out[base]) = r;
}

// ---------------- launch -----------------------------------------------------
extern "C" void kernel_launch(void* const* d_in, const int* in_sizes, int n_in,
                              void* d_out, int out_size) {
    const float* x     = (const float*)d_in[0];
    const float* Wq    = (const float*)d_in[1];
    const float* bq    = (const float*)d_in[2];
    const float* Wv    = (const float*)d_in[3];
    const float* bv    = (const float*)d_in[4];
    const float* Wo    = (const float*)d_in[5];
    const float* bo    = (const float*)d_in[6];
    const float* gamma = (const float*)d_in[7];
    float* out = (float*)d_out;

    k_qz   <<<dim3(Nn / 128, Bb, 3), 128>>>(x, Wq, bq, Wv, Wo);
    k_flash<<<dim3(Nn / 128, BHh), 256>>>();
    k_gv   <<<dim3(36, BHh), 256>>>(Wq, Wv, bv);
    k_out  <<<dim3(Nn / 64, Bb, 4), 256>>>(Wo, bo, gamma, x, out);
}

// round 17
// speedup vs baseline: 1.4797x; 1.3421x over previous
#include <cuda_runtime.h>
#include <cuda_fp16.h>
#include <math.h>
#include <stdint.h>

#define Bb   4
#define Dd   64
#define Hh   4
#define DHd  16
#define Nn   2304
#define BHh  16   // B*heads

#define LOG2E 1.4426950408889634f
#define SC    0.8493218593f   // sqrt(0.5*log2e)

// ---------------- scratch (device globals) ----------------------------------
__device__ uint32_t d_qb[BHh * Nn * 8];          // q f16x2: [bh][n][k/2], scaled by SC
__device__ float d_qn[BHh * Nn];                 // 0.25*log2e*||q||^2
__device__ __half d_zh[BHh * DHd * Nn];          // Z f16: [bh][c][m]
__device__ float d_u[BHh * Nn * DHd];            // U permuted: row' = (n%36)*64 + n/36
__device__ float d_cat[Bb * Dd * Nn];            // cat_img[b][dd][n]
__device__ float d_bound[1];

__device__ __forceinline__ uint32_t smem_u32(const void* p) {
    return (uint32_t)__cvta_generic_to_shared(p);
}
__device__ __forceinline__ void ldsm4(uint32_t& r0, uint32_t& r1, uint32_t& r2, uint32_t& r3,
                                      uint32_t addr) {
    asm volatile("ldmatrix.sync.aligned.m8n8.x4.shared.b16 {%0,%1,%2,%3}, [%4];"
                 : "=r"(r0), "=r"(r1), "=r"(r2), "=r"(r3) : "r"(addr));
}
// f16-accumulate HMMA: D,C are 2 regs (f16x2 pairs: {row r: c0,c1}, {row r+8: c0,c1})
__device__ __forceinline__ void mma16816hh(uint32_t& d0, uint32_t& d1,
                                           uint32_t a0, uint32_t a1, uint32_t a2, uint32_t a3,
                                           uint32_t b0, uint32_t b1,
                                           uint32_t c0, uint32_t c1) {
    asm volatile("mma.sync.aligned.m16n8k16.row.col.f16.f16.f16.f16 "
                 "{%0,%1},{%2,%3,%4,%5},{%6,%7},{%8,%9};"
                 : "=r"(d0), "=r"(d1)
                 : "r"(a0), "r"(a1), "r"(a2), "r"(a3), "r"(b0), "r"(b1),
                   "r"(c0), "r"(c1));
}
__device__ __forceinline__ uint32_t h2u(__half2 h) {
    return *reinterpret_cast<uint32_t*>(&h);
}
__device__ __forceinline__ __half2 u2h(uint32_t u) {
    return *reinterpret_cast<__half2*>(&u);
}

// ---------------- K_qz: z==0 -> q all heads; z==1 -> Z all heads; z==2 -> bound
__global__ void __launch_bounds__(128) k_qz(const float* __restrict__ x,
                                            const float* __restrict__ Wq,
                                            const float* __restrict__ bq,
                                            const float* __restrict__ Wv,
                                            const float* __restrict__ Wo) {
    __shared__ float sW[Hh * DHd * Dd];   // 4096 floats: all heads
    int tid = threadIdx.x;
    int z = blockIdx.z;
    int b = blockIdx.y;

    if (z == 2) {
        if (blockIdx.x != 0 || blockIdx.y != 0) return;
        __shared__ float red[128];
        __shared__ float sq[Hh], sv[Hh];
        for (int h = 0; h < Hh; h++) {
            float a = 0.f;
            for (int i = tid; i < 1024; i += 128) { float w = Wq[h * 1024 + i]; a += w * w; }
            red[tid] = a; __syncthreads();
            for (int s = 64; s > 0; s >>= 1) { if (tid < s) red[tid] += red[tid + s]; __syncthreads(); }
            if (tid == 0) sq[h] = red[0];
            __syncthreads();
            a = 0.f;
            for (int i = tid; i < 1024; i += 128) { float w = Wv[h * 1024 + i]; a += w * w; }
            red[tid] = a; __syncthreads();
            for (int s = 64; s > 0; s >>= 1) { if (tid < s) red[tid] += red[tid + s]; __syncthreads(); }
            if (tid == 0) sv[h] = red[0];
            __syncthreads();
        }
        float a = 0.f;
        for (int i = tid; i < 4096; i += 128) { float w = Wo[i]; a += w * w; }
        red[tid] = a; __syncthreads();
        for (int s = 64; s > 0; s >>= 1) { if (tid < s) red[tid] += red[tid + s]; __syncthreads(); }
        if (tid == 0) {
            // phi = W0(2304/e), fp32 Newton (fp32 accuracy suffices: bound
            // rel-err ~2e-7 -> output rel-err ~1e-10; the 30-iter DOUBLE
            // Newton cost 30-45us of serial FP64 on the launch critical path)
            float zf = 2304.0f / 2.71828182845904523f;
            float w = logf(zf) - logf(logf(zf));
#pragma unroll
            for (int it = 0; it < 20; it++) {
                float ew = expf(w);
                w = w - (w * ew - zf) / (ew * (w + 1.0f));
            }
            float phi = w;
            float term = sqrtf(sq[0] * sv[0] + sq[1] * sv[1] + sq[2] * sv[2] + sq[3] * sv[3]);
            d_bound[0] = sqrtf(2304.f / 64.f) * (4.f * phi + 1.f) * term * sqrtf(red[0]);
        }
        return;
    }

    for (int i = tid; i < 4096; i += 128) sW[i] = Wq[i];
    __syncthreads();

    if (z == 0) {
        int n = blockIdx.x * 128 + tid;
        const float* xb = x + b * Dd * Nn;
        float xv[Dd];
#pragma unroll
        for (int d = 0; d < Dd; d++) xv[d] = xb[d * Nn + n];
        for (int h = 0; h < Hh; h++) {
            int bh = b * Hh + h;
            float qv[DHd];
            float qn = 0.f;
#pragma unroll
            for (int k = 0; k < DHd; k++) {
                float acc = bq[h * DHd + k];
                const float* w = sW + (h * DHd + k) * Dd;
#pragma unroll
                for (int d = 0; d < Dd; d++) acc += w[d] * xv[d];
                qv[k] = acc;
                qn += acc * acc;
            }
            uint32_t pk[8];
#pragma unroll
            for (int i = 0; i < 8; i++)
                pk[i] = h2u(__floats2half2_rn(SC * qv[2 * i], SC * qv[2 * i + 1]));
            uint4* dst = (uint4*)(d_qb + ((size_t)bh * Nn + n) * 8);
            dst[0] = make_uint4(pk[0], pk[1], pk[2], pk[3]);
            dst[1] = make_uint4(pk[4], pk[5], pk[6], pk[7]);
            d_qn[(size_t)bh * Nn + n] = qn * (0.25f * LOG2E);
        }
    } else {
        int m = blockIdx.x * 128 + tid;
        const float* xr = x + (size_t)b * Dd * Nn + (size_t)m * Dd;
        float xv[Dd];
#pragma unroll
        for (int dc = 0; dc < 16; dc++) {
            float4 v = *(const float4*)(xr + dc * 4);
            xv[dc * 4 + 0] = v.x; xv[dc * 4 + 1] = v.y;
            xv[dc * 4 + 2] = v.z; xv[dc * 4 + 3] = v.w;
        }
        for (int h = 0; h < Hh; h++) {
            int bh = b * Hh + h;
            float acc[DHd];
#pragma unroll
            for (int c = 0; c < DHd; c++) acc[c] = 0.f;
#pragma unroll
            for (int d = 0; d < Dd; d++) {
                float xd = xv[d];
                const float4* rr = (const float4*)(sW + h * 1024 + d * 16);
#pragma unroll
                for (int cc = 0; cc < 4; cc++) {
                    float4 rv = rr[cc];
                    acc[cc * 4 + 0] += xd * rv.x;
                    acc[cc * 4 + 1] += xd * rv.y;
                    acc[cc * 4 + 2] += xd * rv.z;
                    acc[cc * 4 + 3] += xd * rv.w;
                }
            }
#pragma unroll
            for (int c = 0; c < DHd; c++)
                d_zh[((size_t)bh * DHd + c) * Nn + m] = __float2half_rn(acc[c]);
        }
    }
}

// ---------------- K1: flash, all-f16 HMMA + direct h2exp2 --------------------
__global__ void __launch_bounds__(256) k_flash() {
    int bh = blockIdx.y;
    int n0 = blockIdx.x * 128;
    int tid = threadIdx.x;
    int w = tid >> 5, lane = tid & 31;
    int grp = lane >> 3, lr = lane & 7;

    __shared__ __align__(16) __half sQ[128 * 24];     // rows n, pitch 24
    __shared__ __align__(16) __half sK[2][64 * 24];   // rows m, pitch 24
    __shared__ __align__(16) __half sZ[2][16 * 72];   // rows c, pitch 72
    __shared__ uint32_t sKn2[2][32];                  // packed (-qnl_m) half2 pairs

    const uint4* qb4 = (const uint4*)d_qb + (size_t)bh * Nn * 2;
    const __half* zb = d_zh + (size_t)bh * DHd * Nn;
    const float* qnb = d_qn + (size_t)bh * Nn;

    int krow = tid >> 1, khalf = tid & 1;
    int zc = (tid - 128) >> 3, zseg = (tid - 128) & 7;

    {
        int row = tid >> 1, half = tid & 1;
        *(uint4*)(sQ + row * 24 + half * 8) = qb4[(size_t)(n0 + row) * 2 + half];
    }
    if (tid < 128) *(uint4*)(sK[0] + krow * 24 + khalf * 8) = qb4[krow * 2 + khalf];
    else           *(uint4*)(sZ[0] + zc * 72 + zseg * 8) = *(const uint4*)(zb + (size_t)zc * Nn + zseg * 8);
    if (tid < 32) {
        float2 v = *(const float2*)(qnb + 2 * tid);
        sKn2[0][tid] = h2u(__floats2half2_rn(-v.x, -v.y));
    }
    __syncthreads();

    uint32_t qa0, qa1, qa2, qa3;
    {
        uint32_t addr = smem_u32(sQ) + ((w * 16 + (grp & 1) * 8 + lr) * 24 + (grp >> 1) * 8) * 2;
        ldsm4(qa0, qa1, qa2, qa3, addr);
    }
    __half2 nq0h = __float2half2_rn(-qnb[n0 + w * 16 + (lane >> 2)]);
    __half2 nq1h = __float2half2_rn(-qnb[n0 + w * 16 + (lane >> 2) + 8]);

    uint32_t AKb0 = smem_u32(sK[0]) + (((grp >> 1) * 8 + lr) * 24 + (grp & 1) * 8) * 2;
    uint32_t AZb0 = smem_u32(sZ[0]) + ((grp >> 1) * 8 + lr) * 144 + ((grp & 1) * 8) * 2;
    const uint32_t KBUF = 64 * 24 * 2, ZBUF = 16 * 72 * 2;

    uint32_t O2[2][2];   // [n-chunk][row-half], f16x2 accumulators
    const uint32_t ZERO2 = 0u;
#pragma unroll
    for (int u = 0; u < 2; u++) { O2[u][0] = ZERO2; O2[u][1] = ZERO2; }
    float li0 = 0.f, li1 = 0.f;

    for (int t = 0; t < 36; t++) {
        int cur = t & 1;
        uint4 pK, pZ;
        float2 pN;
        if (t < 35) {
            int m0 = (t + 1) * 64;
            if (tid < 128) pK = qb4[(size_t)(m0 + krow) * 2 + khalf];
            else           pZ = *(const uint4*)(zb + (size_t)zc * Nn + m0 + zseg * 8);
            if (tid < 32)  pN = *(const float2*)(qnb + m0 + 2 * tid);
        }

        uint32_t kf[8][2];
#pragma unroll
        for (int s = 0; s < 4; s++) {
            uint32_t r0, r1, r2, r3;
            ldsm4(r0, r1, r2, r3, AKb0 + cur * KBUF + s * 768);
            kf[2 * s][0] = r0; kf[2 * s][1] = r1;
            kf[2 * s + 1][0] = r2; kf[2 * s + 1][1] = r3;
        }

        // S mmas (f16 accum, bias in C) + direct packed exp
        uint32_t pe[8][2];
        __half2 tl0 = u2h(ZERO2), tl1 = u2h(ZERO2);
#pragma unroll
        for (int j = 0; j < 8; j++) {
            __half2 knh = u2h(sKn2[cur][4 * j + (lane & 3)]);
            uint32_t c0 = h2u(__hadd2(nq0h, knh));
            uint32_t c1 = h2u(__hadd2(nq1h, knh));
            uint32_t s0, s1;
            mma16816hh(s0, s1, qa0, qa1, qa2, qa3, kf[j][0], kf[j][1], c0, c1);
            __half2 e01 = h2exp2(u2h(s0));
            __half2 e23 = h2exp2(u2h(s1));
            tl0 = __hadd2(tl0, e01);
            tl1 = __hadd2(tl1, e23);
            pe[j][0] = h2u(e01);
            pe[j][1] = h2u(e23);
        }
        li0 += __low2float(tl0) + __high2float(tl0);
        li1 += __low2float(tl1) + __high2float(tl1);

        // PV mmas (f16 accum; P fragments = exp outputs directly)
#pragma unroll
        for (int s = 0; s < 4; s++) {
            uint32_t z0, z1, z2, z3;
            ldsm4(z0, z1, z2, z3, AZb0 + cur * ZBUF + s * 32);
            mma16816hh(O2[0][0], O2[0][1],
                       pe[2 * s][0], pe[2 * s][1], pe[2 * s + 1][0], pe[2 * s + 1][1],
                       z0, z1, O2[0][0], O2[0][1]);
            mma16816hh(O2[1][0], O2[1][1],
                       pe[2 * s][0], pe[2 * s][1], pe[2 * s + 1][0], pe[2 * s + 1][1],
                       z2, z3, O2[1][0], O2[1][1]);
        }

        if (t < 35) {
            int nxt = 1 - cur;
            if (tid < 128) *(uint4*)(sK[nxt] + krow * 24 + khalf * 8) = pK;
            else           *(uint4*)(sZ[nxt] + zc * 72 + zseg * 8) = pZ;
            if (tid < 32)  sKn2[nxt][tid] = h2u(__floats2half2_rn(-pN.x, -pN.y));
        }
        __syncthreads();
    }

    // unpack O to fp32: O[u][0..3] = (r,c0),(r,c1),(r+8,c0),(r+8,c1)
    float O[2][4];
#pragma unroll
    for (int u = 0; u < 2; u++) {
        float2 lo = __half22float2(u2h(O2[u][0]));
        float2 hi = __half22float2(u2h(O2[u][1]));
        O[u][0] = lo.x; O[u][1] = lo.y; O[u][2] = hi.x; O[u][3] = hi.y;
    }

    // quad-reduce (lanes in quad hold disjoint columns)
#pragma unroll
    for (int off = 2; off >= 1; off >>= 1) {
        li0 += __shfl_xor_sync(0xffffffffu, li0, off);
        li1 += __shfl_xor_sync(0xffffffffu, li1, off);
#pragma unroll
        for (int u = 0; u < 2; u++)
#pragma unroll
            for (int k = 0; k < 4; k++)
                O[u][k] += __shfl_xor_sync(0xffffffffu, O[u][k], off);
    }

    float i0 = 1.f / li0, i1 = 1.f / li1;
    int r0 = n0 + w * 16 + (lane >> 2);
    int r1 = r0 + 8;
    int pr0 = (r0 % 36) * 64 + r0 / 36;
    int pr1 = (r1 % 36) * 64 + r1 / 36;
    int cb = 2 * (lane & 3);
    float* ur0 = d_u + ((size_t)bh * Nn + pr0) * 16;
    float* ur1 = d_u + ((size_t)bh * Nn + pr1) * 16;
    *(float2*)(ur0 + cb)     = make_float2(O[0][0] * i0, O[0][1] * i0);
    *(float2*)(ur0 + cb + 8) = make_float2(O[1][0] * i0, O[1][1] * i0);
    *(float2*)(ur1 + cb)     = make_float2(O[0][2] * i1, O[0][3] * i1);
    *(float2*)(ur1 + cb + 8) = make_float2(O[1][2] * i1, O[1][3] * i1);
}

// ---------------- K_gv: fused g/v, writes directly into cat layout ----------
__global__ void __launch_bounds__(256) k_gv(const float* __restrict__ Wq,
                                            const float* __restrict__ Wv,
                                            const float* __restrict__ bv) {
    int bh = blockIdx.y;
    int h = bh & 3;
    int b = bh >> 2;
    int a = blockIdx.x;
    int tid = threadIdx.x;

    __shared__ float sT[64][17];
    __shared__ float sWv[1024];
    __shared__ float sR[64][17];
    __shared__ float sM[16][17];

    int r_ = tid & 63, kg_ = tid >> 6;
    float bvv[4];
#pragma unroll
    for (int kk2 = 0; kk2 < 4; kk2++) bvv[kk2] = bv[h * 16 + kg_ * 4 + kk2];

    {
        int dd = tid >> 2, cg = tid & 3;
        float4 v = *(const float4*)(d_u + ((size_t)bh * Nn + a * 64 + dd) * 16 + cg * 4);
        sT[dd][cg * 4 + 0] = v.x; sT[dd][cg * 4 + 1] = v.y;
        sT[dd][cg * 4 + 2] = v.z; sT[dd][cg * 4 + 3] = v.w;
        float4 rv = *(const float4*)(Wq + h * 1024 + dd * 16 + cg * 4);
        sR[dd][cg * 4 + 0] = rv.x; sR[dd][cg * 4 + 1] = rv.y;
        sR[dd][cg * 4 + 2] = rv.z; sR[dd][cg * 4 + 3] = rv.w;
    }
    for (int i = tid; i < 1024; i += 256) sWv[i] = Wv[h * 1024 + i];
    __syncthreads();

    {
        int k = tid >> 4, c = tid & 15;
        float acc = 0.f;
#pragma unroll
        for (int dd = 0; dd < 64; dd++) acc += sWv[k * 64 + dd] * sT[dd][c];
        sM[k][c] = acc;
    }
    __syncthreads();

    {
        float vacc[4] = {0.f, 0.f, 0.f, 0.f};
#pragma unroll
        for (int c = 0; c < 16; c++) {
            float rc = sR[r_][c];
            vacc[0] += sM[kg_ * 4 + 0][c] * rc;
            vacc[1] += sM[kg_ * 4 + 1][c] * rc;
            vacc[2] += sM[kg_ * 4 + 2][c] * rc;
            vacc[3] += sM[kg_ * 4 + 3][c] * rc;
        }
        int rq = r_ >> 4, kkl = r_ & 15;
#pragma unroll
        for (int kk2 = 0; kk2 < 4; kk2++) {
            int k = kg_ * 4 + kk2;
            float val = bvv[kk2] + 0.25f * vacc[kk2];
            int s = k * 144 + a * 4 + rq;
            int dd_c = s / 36;
            int a_c = s - dd_c * 36;
            int n_c = a_c * 64 + h * 16 + kkl;
            d_cat[((size_t)(b * 64 + dd_c)) * Nn + n_c] = val;
        }
    }
}

// ---------------- K_out: 64(n) x 16(o) tiles, 576 blocks, early x prefetch --
__global__ void __launch_bounds__(256) k_out(const float* __restrict__ Wo,
                                             const float* __restrict__ bo,
                                             const float* __restrict__ gamma,
                                             const float* __restrict__ x,
                                             float* __restrict__ out) {
    int b = blockIdx.y;
    int n0 = blockIdx.x * 64;
    int ob = blockIdx.z * 16;
    int tid = threadIdx.x, ty = tid >> 4, tx = tid & 15;
    __shared__ __align__(16) float sC[64][68];
    __shared__ __align__(16) float sW[16][64];

    int o = ob + ty;
    size_t base = ((size_t)b * 64 + o) * Nn + n0 + tx * 4;
    float4 xin = *(const float4*)(&x[base]);
    float g0 = gamma[0];
    float bnd = d_bound[0];
    float bb = bo[o];

    for (int i = tid; i < 1024; i += 256) {
        int dd = i >> 4, jj = (i & 15) * 4;
        *(float4*)(&sC[dd][jj]) = *(const float4*)(d_cat + ((size_t)(b * 64 + dd)) * Nn + n0 + jj);
    }
    {
        int row = tid >> 4, col = (tid & 15) * 4;
        *(float4*)(&sW[row][col]) = *(const float4*)(Wo + (ob + row) * 64 + col);
    }
    __syncthreads();
    float a0 = 0.f, a1 = 0.f, a2 = 0.f, a3 = 0.f;
#pragma unroll 16
    for (int dd = 0; dd < 64; dd++) {
        float wv = sW[ty][dd];
        float4 cv = *(const float4*)(&sC[dd][tx * 4]);
        a0 += wv * cv.x;
        a1 += wv * cv.y;
        a2 += wv * cv.z;
        a3 += wv * cv.w;
    }
    float scale = g0 / bnd;
    float4 r;
    r.x = scale * (a0 + bb) + xin.x;
    r.y = scale * (a1 + bb) + xin.y;
    r.z = scale * (a2 + bb) + xin.z;
    r.w = scale * (a3 + bb) + xin.w;
    *(float4*)(&out[base]) = r;
}

// ---------------- launch -----------------------------------------------------
extern "C" void kernel_launch(void* const* d_in, const int* in_sizes, int n_in,
                              void* d_out, int out_size) {
    const float* x     = (const float*)d_in[0];
    const float* Wq    = (const float*)d_in[1];
    const float* bq    = (const float*)d_in[2];
    const float* Wv    = (const float*)d_in[3];
    const float* bv    = (const float*)d_in[4];
    const float* Wo    = (const float*)d_in[5];
    const float* bo    = (const float*)d_in[6];
    const float* gamma = (const float*)d_in[7];
    float* out = (float*)d_out;

    k_qz   <<<dim3(Nn / 128, Bb, 3), 128>>>(x, Wq, bq, Wv, Wo);
    k_flash<<<dim3(Nn / 128, BHh), 256>>>();
    k_gv   <<<dim3(36, BHh), 256>>>(Wq, Wv, bv);
    k_out  <<<dim3(Nn / 64, Bb, 4), 256>>>(Wo, bo, gamma, x, out);
}